// round 10
// baseline (speedup 1.0000x reference)
#include <cuda_runtime.h>
#include <cstdint>

// state: [2, 4096, 512] float32. The 4 CNOTs compose into one bit-twiddle
// permutation of the 4096 row indices. GATHER: out[n,i,:] = in[n,src(i),:],
// rows = 512 floats = 2048 B contiguous.
//
// R9: R7 datapath (v8.f32 256-bit accesses, 2 independent chunks/thread,
// single wave) repartitioned as 2048 blocks x 128 threads: small CTAs ->
// ~14 resident CTAs/SM, higher warp residency, finer tail.

static __device__ __forceinline__ unsigned src_index(unsigned j) {
    // PAIRS [(0,1),(2,3),(5,2),(11,7)] applied in reverse for the source map
    // (big-endian: qubit q -> bit 11-q)
    j ^= ((j >> 0) & 1u) << 4;    // (c=11, t=7)
    j ^= ((j >> 6) & 1u) << 9;    // (c=5,  t=2)
    j ^= ((j >> 9) & 1u) << 8;    // (c=2,  t=3)
    j ^= ((j >> 11) & 1u) << 10;  // (c=0,  t=1)
    return j;
}

// 2^19 v8 (32B) chunks total. 2048 blocks x 128 threads x 2 chunks/thread.
// Chunk k at stride 2^18 -> both loads independent; warp accesses fully
// contiguous (1 KB per warp per round).
__global__ __launch_bounds__(128) void cnot_perm_copy_v8x2_sm(
    const float* __restrict__ in, float* __restrict__ out)
{
    unsigned base = blockIdx.x * blockDim.x + threadIdx.x;  // 0 .. 2^18-1

    const float* gsrc[2];
    float*       gdst[2];
    #pragma unroll
    for (int k = 0; k < 2; k++) {
        unsigned idx = base + (unsigned)k * (1u << 18);     // 0 .. 2^19-1
        unsigned c8  = idx & 63u;        // 32B chunk within row
        unsigned row = idx >> 6;         // 0 .. 8191
        unsigned i   = row & 4095u;
        unsigned n   = row >> 12;
        unsigned src = (n << 12) | src_index(i);
        gsrc[k] = in  + ((size_t)src * 512u + c8 * 8u);
        gdst[k] = out + ((size_t)row * 512u + c8 * 8u);
    }

    float a0,a1,a2,a3,a4,a5,a6,a7;
    float b0,b1,b2,b3,b4,b5,b6,b7;
    asm volatile("ld.global.nc.v8.f32 {%0,%1,%2,%3,%4,%5,%6,%7}, [%8];"
        : "=f"(a0),"=f"(a1),"=f"(a2),"=f"(a3),
          "=f"(a4),"=f"(a5),"=f"(a6),"=f"(a7) : "l"(gsrc[0]));
    asm volatile("ld.global.nc.v8.f32 {%0,%1,%2,%3,%4,%5,%6,%7}, [%8];"
        : "=f"(b0),"=f"(b1),"=f"(b2),"=f"(b3),
          "=f"(b4),"=f"(b5),"=f"(b6),"=f"(b7) : "l"(gsrc[1]));
    asm volatile("st.global.v8.f32 [%0], {%1,%2,%3,%4,%5,%6,%7,%8};"
        :: "l"(gdst[0]),
           "f"(a0),"f"(a1),"f"(a2),"f"(a3),
           "f"(a4),"f"(a5),"f"(a6),"f"(a7) : "memory");
    asm volatile("st.global.v8.f32 [%0], {%1,%2,%3,%4,%5,%6,%7,%8};"
        :: "l"(gdst[1]),
           "f"(b0),"f"(b1),"f"(b2),"f"(b3),
           "f"(b4),"f"(b5),"f"(b6),"f"(b7) : "memory");
}

extern "C" void kernel_launch(void* const* d_in, const int* in_sizes, int n_in,
                              void* d_out, int out_size) {
    const float* in  = (const float*)d_in[0];
    float*       out = (float*)d_out;
    // 2^19 chunks / (128 threads * 2) = 2048 blocks
    cnot_perm_copy_v8x2_sm<<<2048, 128>>>(in, out);
}

// round 11
// speedup vs baseline: 1.6062x; 1.6062x over previous
#include <cuda_runtime.h>
#include <cstdint>

// state: [2, 4096, 512] float32. The 4 CNOTs compose into one bit-twiddle
// permutation of the 4096 row indices. GATHER: out[n,i,:] = in[n,src(i),:],
// rows = 512 floats = 2048 B contiguous.
//
// FINAL (R7 config — empirical optimum over 9 measured variants):
// 256-bit v8.f32 accesses, 2 independent chunks per thread (MLP=2),
// 1024 blocks x 256 threads (single wave on 148 SMs).
//
// Why this is the floor: the cold kernel already runs at the LTS chip cap
// (48 MB of L2 crossings / 7.1 us = 6.8 TB/s ~= 6300 B/cyc path-independent
// ceiling). LDG, TMA-bulk, and scatter variants all converge to the same
// duration because they share that wall.

static __device__ __forceinline__ unsigned src_index(unsigned j) {
    // PAIRS [(0,1),(2,3),(5,2),(11,7)] applied in reverse for the source map
    // (big-endian: qubit q -> bit 11-q)
    j ^= ((j >> 0) & 1u) << 4;    // (c=11, t=7)
    j ^= ((j >> 6) & 1u) << 9;    // (c=5,  t=2)
    j ^= ((j >> 9) & 1u) << 8;    // (c=2,  t=3)
    j ^= ((j >> 11) & 1u) << 10;  // (c=0,  t=1)
    return j;
}

// 2^19 v8 (32B) chunks total. 1024 blocks x 256 threads x 2 chunks/thread.
// Chunk k at stride 2^18 -> both loads independent; warp accesses fully
// contiguous (1 KB per warp per round).
__global__ __launch_bounds__(256) void cnot_perm_copy_v8x2(
    const float* __restrict__ in, float* __restrict__ out)
{
    unsigned base = blockIdx.x * blockDim.x + threadIdx.x;  // 0 .. 2^18-1

    const float* gsrc[2];
    float*       gdst[2];
    #pragma unroll
    for (int k = 0; k < 2; k++) {
        unsigned idx = base + (unsigned)k * (1u << 18);     // 0 .. 2^19-1
        unsigned c8  = idx & 63u;        // 32B chunk within row
        unsigned row = idx >> 6;         // 0 .. 8191
        unsigned i   = row & 4095u;
        unsigned n   = row >> 12;
        unsigned src = (n << 12) | src_index(i);
        gsrc[k] = in  + ((size_t)src * 512u + c8 * 8u);
        gdst[k] = out + ((size_t)row * 512u + c8 * 8u);
    }

    float a0,a1,a2,a3,a4,a5,a6,a7;
    float b0,b1,b2,b3,b4,b5,b6,b7;
    asm volatile("ld.global.nc.v8.f32 {%0,%1,%2,%3,%4,%5,%6,%7}, [%8];"
        : "=f"(a0),"=f"(a1),"=f"(a2),"=f"(a3),
          "=f"(a4),"=f"(a5),"=f"(a6),"=f"(a7) : "l"(gsrc[0]));
    asm volatile("ld.global.nc.v8.f32 {%0,%1,%2,%3,%4,%5,%6,%7}, [%8];"
        : "=f"(b0),"=f"(b1),"=f"(b2),"=f"(b3),
          "=f"(b4),"=f"(b5),"=f"(b6),"=f"(b7) : "l"(gsrc[1]));
    asm volatile("st.global.v8.f32 [%0], {%1,%2,%3,%4,%5,%6,%7,%8};"
        :: "l"(gdst[0]),
           "f"(a0),"f"(a1),"f"(a2),"f"(a3),
           "f"(a4),"f"(a5),"f"(a6),"f"(a7) : "memory");
    asm volatile("st.global.v8.f32 [%0], {%1,%2,%3,%4,%5,%6,%7,%8};"
        :: "l"(gdst[1]),
           "f"(b0),"f"(b1),"f"(b2),"f"(b3),
           "f"(b4),"f"(b5),"f"(b6),"f"(b7) : "memory");
}

extern "C" void kernel_launch(void* const* d_in, const int* in_sizes, int n_in,
                              void* d_out, int out_size) {
    const float* in  = (const float*)d_in[0];
    float*       out = (float*)d_out;
    // 2^19 chunks / (256 threads * 2) = 1024 blocks (single wave)
    cnot_perm_copy_v8x2<<<1024, 256>>>(in, out);
}